// round 6
// baseline (speedup 1.0000x reference)
#include <cuda_runtime.h>
#include <cuda_bf16.h>
#include <cstdint>
#include <math.h>

#define BB   2048
#define TT   80
#define HH   512
#define EMBD 100
#define K1P  128            // EMB padded to 128 for clean BK=32 tiling
#define MT   (BB*TT)        // 163840 rows

// ---- scratch (device globals: allocation-free rule) ----
__device__ __nv_bfloat16 g_bufA[(size_t)MT * HH];   // activations ping
__device__ __nv_bfloat16 g_bufB[(size_t)MT * HH];   // activations pong
__device__ float         g_Z[(size_t)MT * HH];      // Z = xW+b, fp32
__device__ __nv_bfloat16 g_W1bf[K1P * HH];          // W1 padded [128,512]
__device__ __nv_bfloat16 g_Wbf[3 * HH * HH];        // W2,W3,W4
__device__ __nv_bfloat16 g_Ubf[4 * HH * HH];        // U1..U4

// ---------------------------------------------------------------------------
__global__ void convert_weights_kernel(
    const float* __restrict__ W1, const float* __restrict__ W2,
    const float* __restrict__ W3, const float* __restrict__ W4,
    const float* __restrict__ U1, const float* __restrict__ U2,
    const float* __restrict__ U3, const float* __restrict__ U4)
{
    int i = blockIdx.x * blockDim.x + threadIdx.x;
    if (i < K1P * HH) {
        int r = i / HH, c = i % HH;
        g_W1bf[i] = __float2bfloat16(r < EMBD ? W1[r * HH + c] : 0.f);
    }
    if (i < HH * HH) {
        g_Wbf[i]               = __float2bfloat16(W2[i]);
        g_Wbf[HH * HH + i]     = __float2bfloat16(W3[i]);
        g_Wbf[2 * HH * HH + i] = __float2bfloat16(W4[i]);
        g_Ubf[i]               = __float2bfloat16(U1[i]);
        g_Ubf[HH * HH + i]     = __float2bfloat16(U2[i]);
        g_Ubf[2 * HH * HH + i] = __float2bfloat16(U3[i]);
        g_Ubf[3 * HH * HH + i] = __float2bfloat16(U4[i]);
    }
}

// Embedding gather, time-major [t*BB + b, K1P], zero-padded cols 100..127
__global__ void embed_kernel(const int* __restrict__ tokens,
                             const float* __restrict__ emb)
{
    long i = (long)blockIdx.x * blockDim.x + threadIdx.x;
    if (i >= (long)MT * K1P) return;
    int row = (int)(i / K1P);
    int c   = (int)(i % K1P);
    int t = row / BB, b = row % BB;
    float v = 0.f;
    if (c < EMBD) v = emb[(long)tokens[b * TT + t] * EMBD + c];
    g_bufA[i] = __float2bfloat16(v);
}

// ---------------------------------------------------------------------------
__device__ __forceinline__ uint32_t smem_u32(const void* p) {
    return (uint32_t)__cvta_generic_to_shared(p);
}

// C = A(bf16,[M,K] row-major, leading dim lda) @ B(bf16,[K,512] row-major)
// EPI==0: outZ = C + bias        (fp32)
// EPI==1: outH = tanh(C + Zin)   (bf16)
// Block tile 128x64, BK=32, 8 warps (4m x 2n), warp tile 32x32, mma m16n8k16.
template <int EPI>
__global__ __launch_bounds__(256) void gemm_kernel(
    const __nv_bfloat16* __restrict__ A, int lda, int K,
    const __nv_bfloat16* __restrict__ Bm,
    const float* __restrict__ bias,
    const float* __restrict__ Zin,
    float* __restrict__ outZ,
    __nv_bfloat16* __restrict__ outH)
{
    constexpr int BM = 128, BN = 64, BK = 32;
    __shared__ __nv_bfloat16 As[BM][BK + 8];   // pad: conflict-free LDSM
    __shared__ __nv_bfloat16 Bs[BK][BN + 8];

    const int tid  = threadIdx.x;
    const int warp = tid >> 5, lane = tid & 31;
    const int wm = warp >> 1, wn = warp & 1;
    const long rowBase = (long)blockIdx.x * BM;
    const int  colBase = blockIdx.y * BN;

    float acc[2][4][4];
#pragma unroll
    for (int m = 0; m < 2; m++)
#pragma unroll
        for (int j = 0; j < 4; j++)
#pragma unroll
            for (int q = 0; q < 4; q++) acc[m][j][q] = 0.f;

    const int a_r0 = tid >> 2, a_ch = tid & 3;   // A: 128 rows x 4 x16B chunks
    const int b_r  = tid >> 3, b_ch = tid & 7;   // B: 32 rows x 8 x16B chunks

    const int nkt = K / BK;
    for (int kt = 0; kt < nkt; kt++) {
        const int k0 = kt * BK;
#pragma unroll
        for (int p = 0; p < 2; p++) {
            int r = a_r0 + p * 64;
            *reinterpret_cast<uint4*>(&As[r][a_ch * 8]) =
                *reinterpret_cast<const uint4*>(A + (rowBase + r) * lda + k0 + a_ch * 8);
        }
        *reinterpret_cast<uint4*>(&Bs[b_r][b_ch * 8]) =
            *reinterpret_cast<const uint4*>(Bm + (long)(k0 + b_r) * HH + colBase + b_ch * 8);
        __syncthreads();

#pragma unroll
        for (int ks = 0; ks < 2; ks++) {
            uint32_t a[2][4], b[2][4];
#pragma unroll
            for (int m = 0; m < 2; m++) {
                uint32_t addr = smem_u32(&As[wm * 32 + m * 16 + (lane & 15)][ks * 16 + (lane >> 4) * 8]);
                asm volatile("ldmatrix.sync.aligned.m8n8.x4.shared.b16 {%0,%1,%2,%3}, [%4];"
                             : "=r"(a[m][0]), "=r"(a[m][1]), "=r"(a[m][2]), "=r"(a[m][3])
                             : "r"(addr));
            }
#pragma unroll
            for (int jj = 0; jj < 2; jj++) {
                uint32_t addr = smem_u32(&Bs[ks * 16 + (lane & 15)][wn * 32 + jj * 16 + (lane >> 4) * 8]);
                asm volatile("ldmatrix.sync.aligned.m8n8.x4.trans.shared.b16 {%0,%1,%2,%3}, [%4];"
                             : "=r"(b[jj][0]), "=r"(b[jj][1]), "=r"(b[jj][2]), "=r"(b[jj][3])
                             : "r"(addr));
            }
#pragma unroll
            for (int m = 0; m < 2; m++)
#pragma unroll
                for (int j = 0; j < 4; j++) {
                    uint32_t b0 = b[j >> 1][(j & 1) * 2 + 0];
                    uint32_t b1 = b[j >> 1][(j & 1) * 2 + 1];
                    asm volatile(
                        "mma.sync.aligned.m16n8k16.row.col.f32.bf16.bf16.f32 "
                        "{%0,%1,%2,%3}, {%4,%5,%6,%7}, {%8,%9}, {%0,%1,%2,%3};"
                        : "+f"(acc[m][j][0]), "+f"(acc[m][j][1]),
                          "+f"(acc[m][j][2]), "+f"(acc[m][j][3])
                        : "r"(a[m][0]), "r"(a[m][1]), "r"(a[m][2]), "r"(a[m][3]),
                          "r"(b0), "r"(b1));
                }
        }
        __syncthreads();
    }

    // epilogue (mma C frag: row = lane/4 (+8), col = 2*(lane%4) (+1))
    const int r0 = lane >> 2, c0 = (lane & 3) * 2;
#pragma unroll
    for (int m = 0; m < 2; m++)
#pragma unroll
        for (int j = 0; j < 4; j++) {
            long grow = rowBase + wm * 32 + m * 16 + r0;
            int  gcol = colBase + wn * 32 + j * 8 + c0;
            if (EPI == 0) {
                float bv0 = bias[gcol], bv1 = bias[gcol + 1];
                outZ[grow * HH + gcol]           = acc[m][j][0] + bv0;
                outZ[grow * HH + gcol + 1]       = acc[m][j][1] + bv1;
                outZ[(grow + 8) * HH + gcol]     = acc[m][j][2] + bv0;
                outZ[(grow + 8) * HH + gcol + 1] = acc[m][j][3] + bv1;
            } else {
                outH[grow * HH + gcol] =
                    __float2bfloat16(tanhf(acc[m][j][0] + Zin[grow * HH + gcol]));
                outH[grow * HH + gcol + 1] =
                    __float2bfloat16(tanhf(acc[m][j][1] + Zin[grow * HH + gcol + 1]));
                outH[(grow + 8) * HH + gcol] =
                    __float2bfloat16(tanhf(acc[m][j][2] + Zin[(grow + 8) * HH + gcol]));
                outH[(grow + 8) * HH + gcol + 1] =
                    __float2bfloat16(tanhf(acc[m][j][3] + Zin[(grow + 8) * HH + gcol + 1]));
            }
        }
}

// t = 0: h0 = 0 -> H0 = tanh(Z0) elementwise
__global__ void step0_kernel(const float* __restrict__ Z, __nv_bfloat16* __restrict__ Hout)
{
    int i = blockIdx.x * blockDim.x + threadIdx.x;
    if (i < BB * HH) Hout[i] = __float2bfloat16(tanhf(Z[i]));
}

// out = sigmoid(Hlast @ Wo + bo), one warp per row
__global__ void head_kernel(const __nv_bfloat16* __restrict__ Hl,
                            const float* __restrict__ Wo,
                            const float* __restrict__ bo,
                            float* __restrict__ out)
{
    int row  = blockIdx.x * 8 + (threadIdx.x >> 5);
    int lane = threadIdx.x & 31;
    float s = 0.f;
    for (int j = lane; j < HH; j += 32)
        s += __bfloat162float(Hl[(long)row * HH + j]) * Wo[j];
#pragma unroll
    for (int o = 16; o > 0; o >>= 1) s += __shfl_xor_sync(0xffffffffu, s, o);
    if (lane == 0) out[row] = 1.f / (1.f + expf(-(s + bo[0])));
}

// ---------------------------------------------------------------------------
extern "C" void kernel_launch(void* const* d_in, const int* in_sizes, int n_in,
                              void* d_out, int out_size)
{
    const int*   tokens = (const int*)d_in[0];
    const float* emb = (const float*)d_in[1];
    const float* W1 = (const float*)d_in[2];
    const float* U1 = (const float*)d_in[3];
    const float* b1 = (const float*)d_in[4];
    const float* W2 = (const float*)d_in[5];
    const float* U2 = (const float*)d_in[6];
    const float* b2 = (const float*)d_in[7];
    const float* W3 = (const float*)d_in[8];
    const float* U3 = (const float*)d_in[9];
    const float* b3 = (const float*)d_in[10];
    const float* W4 = (const float*)d_in[11];
    const float* U4 = (const float*)d_in[12];
    const float* b4 = (const float*)d_in[13];
    const float* Wo = (const float*)d_in[14];
    const float* bo = (const float*)d_in[15];
    float* out = (float*)d_out;

    __nv_bfloat16 *bufA, *bufB, *W1bf, *Wbf, *Ubf;
    float* Zbuf;
    cudaGetSymbolAddress((void**)&bufA, g_bufA);
    cudaGetSymbolAddress((void**)&bufB, g_bufB);
    cudaGetSymbolAddress((void**)&W1bf, g_W1bf);
    cudaGetSymbolAddress((void**)&Wbf, g_Wbf);
    cudaGetSymbolAddress((void**)&Ubf, g_Ubf);
    cudaGetSymbolAddress((void**)&Zbuf, g_Z);

    const dim3 blk(256);
    convert_weights_kernel<<<(HH * HH + 255) / 256, blk>>>(W1, W2, W3, W4, U1, U2, U3, U4);
    embed_kernel<<<(int)(((long)MT * K1P + 255) / 256), blk>>>(tokens, emb);

    const dim3 gridBig(MT / 128, 8);
    const dim3 gridStep(BB / 128, 8);
    const size_t stepStride = (size_t)BB * HH;

    // -------- layer 1 --------
    gemm_kernel<0><<<gridBig, blk>>>(bufA, K1P, K1P, W1bf, b1, nullptr, Zbuf, nullptr);
    step0_kernel<<<(BB * HH) / 256, blk>>>(Zbuf, bufB);
    for (int t = 1; t < TT; t++)
        gemm_kernel<1><<<gridStep, blk>>>(bufB + (size_t)(t - 1) * stepStride, HH, HH,
                                          Ubf, nullptr, Zbuf + (size_t)t * stepStride,
                                          nullptr, bufB + (size_t)t * stepStride);

    // -------- layers 2..4 --------
    const float* biases[4] = {b1, b2, b3, b4};
    __nv_bfloat16* Xin  = bufB;
    __nv_bfloat16* Hout = bufA;
    for (int l = 1; l < 4; l++) {
        gemm_kernel<0><<<gridBig, blk>>>(Xin, HH, HH, Wbf + (size_t)(l - 1) * HH * HH,
                                         biases[l], nullptr, Zbuf, nullptr);
        step0_kernel<<<(BB * HH) / 256, blk>>>(Zbuf, Hout);
        for (int t = 1; t < TT; t++)
            gemm_kernel<1><<<gridStep, blk>>>(Hout + (size_t)(t - 1) * stepStride, HH, HH,
                                              Ubf + (size_t)l * HH * HH, nullptr,
                                              Zbuf + (size_t)t * stepStride,
                                              nullptr, Hout + (size_t)t * stepStride);
        __nv_bfloat16* tmp = Xin; Xin = Hout; Hout = tmp;
    }

    // final hidden state lives in Xin (last swap), timestep TT-1
    head_kernel<<<BB / 8, blk>>>(Xin + (size_t)(TT - 1) * stepStride, Wo, bo, out);
}

// round 9
// speedup vs baseline: 1.2483x; 1.2483x over previous
#include <cuda_runtime.h>
#include <cuda_bf16.h>
#include <cstdint>
#include <math.h>

#define BB   2048
#define TT   80
#define HH   512
#define EMBD 100
#define K1P  128            // EMB padded to 128 for clean BK=32 tiling
#define MT   (BB*TT)        // 163840 rows
#define NCTAS 128           // persistent kernel grid (16 row-blocks x 8 col-blocks)

// ---- scratch (device globals: allocation-free rule) ----
__device__ __nv_bfloat16 g_bufA[(size_t)MT * HH];   // activations ping
__device__ __nv_bfloat16 g_bufB[(size_t)MT * HH];   // activations pong
__device__ float         g_Z[(size_t)MT * HH];      // Z = xW+b, fp32
__device__ __nv_bfloat16 g_W1bf[K1P * HH];          // W1 padded [128,512]
__device__ __nv_bfloat16 g_Wbf[3 * HH * HH];        // W2,W3,W4
__device__ __nv_bfloat16 g_Ubf[4 * HH * HH];        // U1..U4

// grid-barrier state (sense via monotonically increasing generation)
__device__ unsigned g_barArrive = 0;
__device__ unsigned g_barGen    = 0;

// ---------------------------------------------------------------------------
__global__ void convert_weights_kernel(
    const float* __restrict__ W1, const float* __restrict__ W2,
    const float* __restrict__ W3, const float* __restrict__ W4,
    const float* __restrict__ U1, const float* __restrict__ U2,
    const float* __restrict__ U3, const float* __restrict__ U4)
{
    int i = blockIdx.x * blockDim.x + threadIdx.x;
    if (i < K1P * HH) {
        int r = i / HH, c = i % HH;
        g_W1bf[i] = __float2bfloat16(r < EMBD ? W1[r * HH + c] : 0.f);
    }
    if (i < HH * HH) {
        g_Wbf[i]               = __float2bfloat16(W2[i]);
        g_Wbf[HH * HH + i]     = __float2bfloat16(W3[i]);
        g_Wbf[2 * HH * HH + i] = __float2bfloat16(W4[i]);
        g_Ubf[i]               = __float2bfloat16(U1[i]);
        g_Ubf[HH * HH + i]     = __float2bfloat16(U2[i]);
        g_Ubf[2 * HH * HH + i] = __float2bfloat16(U3[i]);
        g_Ubf[3 * HH * HH + i] = __float2bfloat16(U4[i]);
    }
}

// Embedding gather, time-major [t*BB + b, K1P], zero-padded cols 100..127
__global__ void embed_kernel(const int* __restrict__ tokens,
                             const float* __restrict__ emb)
{
    long i = (long)blockIdx.x * blockDim.x + threadIdx.x;
    if (i >= (long)MT * K1P) return;
    int row = (int)(i / K1P);
    int c   = (int)(i % K1P);
    int t = row / BB, b = row % BB;
    float v = 0.f;
    if (c < EMBD) v = emb[(long)tokens[b * TT + t] * EMBD + c];
    g_bufA[i] = __float2bfloat16(v);
}

// ---------------------------------------------------------------------------
__device__ __forceinline__ uint32_t smem_u32(const void* p) {
    return (uint32_t)__cvta_generic_to_shared(p);
}

// ---------------------------------------------------------------------------
// Big GEMM (Z = X @ W + b), unchanged from previous round (parallel over all t).
// Block tile 128x64, BK=32, 8 warps (4m x 2n), warp tile 32x32, mma m16n8k16.
__global__ __launch_bounds__(256) void gemm_z_kernel(
    const __nv_bfloat16* __restrict__ A, int lda, int K,
    const __nv_bfloat16* __restrict__ Bm,
    const float* __restrict__ bias,
    float* __restrict__ outZ)
{
    constexpr int BM = 128, BN = 64, BK = 32;
    __shared__ __nv_bfloat16 As[BM][BK + 8];
    __shared__ __nv_bfloat16 Bs[BK][BN + 8];

    const int tid  = threadIdx.x;
    const int warp = tid >> 5, lane = tid & 31;
    const int wm = warp >> 1, wn = warp & 1;
    const long rowBase = (long)blockIdx.x * BM;
    const int  colBase = blockIdx.y * BN;

    float acc[2][4][4];
#pragma unroll
    for (int m = 0; m < 2; m++)
#pragma unroll
        for (int j = 0; j < 4; j++)
#pragma unroll
            for (int q = 0; q < 4; q++) acc[m][j][q] = 0.f;

    const int a_r0 = tid >> 2, a_ch = tid & 3;
    const int b_r  = tid >> 3, b_ch = tid & 7;

    const int nkt = K / BK;
    for (int kt = 0; kt < nkt; kt++) {
        const int k0 = kt * BK;
#pragma unroll
        for (int p = 0; p < 2; p++) {
            int r = a_r0 + p * 64;
            *reinterpret_cast<uint4*>(&As[r][a_ch * 8]) =
                *reinterpret_cast<const uint4*>(A + (rowBase + r) * lda + k0 + a_ch * 8);
        }
        *reinterpret_cast<uint4*>(&Bs[b_r][b_ch * 8]) =
            *reinterpret_cast<const uint4*>(Bm + (long)(k0 + b_r) * HH + colBase + b_ch * 8);
        __syncthreads();

#pragma unroll
        for (int ks = 0; ks < 2; ks++) {
            uint32_t a[2][4], b[2][4];
#pragma unroll
            for (int m = 0; m < 2; m++) {
                uint32_t addr = smem_u32(&As[wm * 32 + m * 16 + (lane & 15)][ks * 16 + (lane >> 4) * 8]);
                asm volatile("ldmatrix.sync.aligned.m8n8.x4.shared.b16 {%0,%1,%2,%3}, [%4];"
                             : "=r"(a[m][0]), "=r"(a[m][1]), "=r"(a[m][2]), "=r"(a[m][3])
                             : "r"(addr));
            }
#pragma unroll
            for (int jj = 0; jj < 2; jj++) {
                uint32_t addr = smem_u32(&Bs[ks * 16 + (lane & 15)][wn * 32 + jj * 16 + (lane >> 4) * 8]);
                asm volatile("ldmatrix.sync.aligned.m8n8.x4.trans.shared.b16 {%0,%1,%2,%3}, [%4];"
                             : "=r"(b[jj][0]), "=r"(b[jj][1]), "=r"(b[jj][2]), "=r"(b[jj][3])
                             : "r"(addr));
            }
#pragma unroll
            for (int m = 0; m < 2; m++)
#pragma unroll
                for (int j = 0; j < 4; j++) {
                    uint32_t b0 = b[j >> 1][(j & 1) * 2 + 0];
                    uint32_t b1 = b[j >> 1][(j & 1) * 2 + 1];
                    asm volatile(
                        "mma.sync.aligned.m16n8k16.row.col.f32.bf16.bf16.f32 "
                        "{%0,%1,%2,%3}, {%4,%5,%6,%7}, {%8,%9}, {%0,%1,%2,%3};"
                        : "+f"(acc[m][j][0]), "+f"(acc[m][j][1]),
                          "+f"(acc[m][j][2]), "+f"(acc[m][j][3])
                        : "r"(a[m][0]), "r"(a[m][1]), "r"(a[m][2]), "r"(a[m][3]),
                          "r"(b0), "r"(b1));
                }
        }
        __syncthreads();
    }

    const int r0 = lane >> 2, c0 = (lane & 3) * 2;
#pragma unroll
    for (int m = 0; m < 2; m++)
#pragma unroll
        for (int j = 0; j < 4; j++) {
            long grow = rowBase + wm * 32 + m * 16 + r0;
            int  gcol = colBase + wn * 32 + j * 8 + c0;
            float bv0 = bias[gcol], bv1 = bias[gcol + 1];
            outZ[grow * HH + gcol]           = acc[m][j][0] + bv0;
            outZ[grow * HH + gcol + 1]       = acc[m][j][1] + bv1;
            outZ[(grow + 8) * HH + gcol]     = acc[m][j][2] + bv0;
            outZ[(grow + 8) * HH + gcol + 1] = acc[m][j][3] + bv1;
        }
}

// ---------------------------------------------------------------------------
// software grid barrier (all NCTAS co-resident; 1 CTA/SM)
__device__ __forceinline__ void grid_barrier()
{
    __threadfence();          // release: this thread's H writes -> L2
    __syncthreads();          // all threads of CTA done + fenced
    if (threadIdx.x == 0) {
        unsigned gen = *(volatile unsigned*)&g_barGen;
        if (atomicAdd(&g_barArrive, 1u) == (unsigned)(NCTAS - 1)) {
            g_barArrive = 0;
            __threadfence();                          // reset before gen bump
            *(volatile unsigned*)&g_barGen = gen + 1; // release all
        } else {
            int it = 0;
            while (*(volatile unsigned*)&g_barGen == gen) {
                if (++it > 32) __nanosleep(64);
            }
        }
        __threadfence();      // acquire side
    }
    __syncthreads();
}

// ---------------------------------------------------------------------------
// Persistent per-layer recurrence: H_t = tanh(H_{t-1} @ U + Z_t), t = 0..79
// (H_{-1} = 0, so step 0 is just tanh(Z_0)).
// Grid = 128 CTAs (16 row-blocks of 128 x 8 col-blocks of 64), 256 threads.
// U[:, col:col+64] stays resident in smem across all timesteps.
// Dynamic smem: As[128][520] + Us[512][72]  (bf16)  = 206,848 B.
#define AS_PITCH 520
#define US_PITCH 72
#define RNN_SMEM ((128 * AS_PITCH + 512 * US_PITCH) * 2)

__global__ __launch_bounds__(256) void rnn_layer_kernel(
    const float* __restrict__ Z,           // [TT][BB][HH] fp32
    __nv_bfloat16* __restrict__ H,         // [TT][BB][HH] bf16 (output)
    const __nv_bfloat16* __restrict__ U)   // [HH][HH] bf16
{
    const int tid  = threadIdx.x;
    const int warp = tid >> 5, lane = tid & 31;
    const int wm = warp >> 1, wn = warp & 1;
    const int rowBase = (blockIdx.x >> 3) * 128;
    const int colBase = (blockIdx.x & 7) * 64;

    extern __shared__ __nv_bfloat16 sh[];
    __nv_bfloat16 (*As)[AS_PITCH] = reinterpret_cast<__nv_bfloat16(*)[AS_PITCH]>(sh);
    __nv_bfloat16 (*Us)[US_PITCH] = reinterpret_cast<__nv_bfloat16(*)[US_PITCH]>(sh + 128 * AS_PITCH);

    // ---- load U slice [512][64] into smem once ----
    for (int i = tid; i < 512 * 8; i += 256) {          // 8 uint4 per row
        int k = i >> 3, ch = i & 7;
        *reinterpret_cast<uint4*>(&Us[k][ch * 8]) =
            *reinterpret_cast<const uint4*>(U + (long)k * HH + colBase + ch * 8);
    }

    // ---- step 0: H0 = tanh(Z0) for our tile ----
    for (int i = tid; i < 128 * 32; i += 256) {         // 2 cols per iter
        int r = i >> 5, c2 = (i & 31) * 2;
        long g = (long)(rowBase + r) * HH + colBase + c2;
        float2 z = *reinterpret_cast<const float2*>(&Z[g]);
        __nv_bfloat162 hv;
        hv.x = __float2bfloat16(tanhf(z.x));
        hv.y = __float2bfloat16(tanhf(z.y));
        *reinterpret_cast<__nv_bfloat162*>(&H[g]) = hv;
    }

    const int r0 = lane >> 2, c0 = (lane & 3) * 2;

    for (int t = 1; t < TT; t++) {
        grid_barrier();   // H_{t-1} fully visible; also guards As reuse

        // ---- load A = H_{t-1}[rowBase:+128][0:512] into smem ----
        const __nv_bfloat16* Ag = H + (long)(t - 1) * BB * HH;
        for (int i = tid; i < 128 * 64; i += 256) {     // 64 uint4 per row
            int r = i >> 6, ch = i & 63;
            *reinterpret_cast<uint4*>(&As[r][ch * 8]) =
                *reinterpret_cast<const uint4*>(Ag + (long)(rowBase + r) * HH + ch * 8);
        }
        __syncthreads();

        // ---- C = A @ Us over K = 512 ----
        float acc[2][4][4];
#pragma unroll
        for (int m = 0; m < 2; m++)
#pragma unroll
            for (int j = 0; j < 4; j++)
#pragma unroll
                for (int q = 0; q < 4; q++) acc[m][j][q] = 0.f;

#pragma unroll 4
        for (int kt = 0; kt < 16; kt++) {
#pragma unroll
            for (int ks = 0; ks < 2; ks++) {
                const int k0 = kt * 32 + ks * 16;
                uint32_t a[2][4], b[2][4];
#pragma unroll
                for (int m = 0; m < 2; m++) {
                    uint32_t addr = smem_u32(&As[wm * 32 + m * 16 + (lane & 15)][k0 + (lane >> 4) * 8]);
                    asm volatile("ldmatrix.sync.aligned.m8n8.x4.shared.b16 {%0,%1,%2,%3}, [%4];"
                                 : "=r"(a[m][0]), "=r"(a[m][1]), "=r"(a[m][2]), "=r"(a[m][3])
                                 : "r"(addr));
                }
#pragma unroll
                for (int jj = 0; jj < 2; jj++) {
                    uint32_t addr = smem_u32(&Us[k0 + (lane & 15)][wn * 32 + jj * 16 + (lane >> 4) * 8]);
                    asm volatile("ldmatrix.sync.aligned.m8n8.x4.trans.shared.b16 {%0,%1,%2,%3}, [%4];"
                                 : "=r"(b[jj][0]), "=r"(b[jj][1]), "=r"(b[jj][2]), "=r"(b[jj][3])
                                 : "r"(addr));
                }
#pragma unroll
                for (int m = 0; m < 2; m++)
#pragma unroll
                    for (int j = 0; j < 4; j++) {
                        uint32_t b0 = b[j >> 1][(j & 1) * 2 + 0];
                        uint32_t b1 = b[j >> 1][(j & 1) * 2 + 1];
                        asm volatile(
                            "mma.sync.aligned.m16n8k16.row.col.f32.bf16.bf16.f32 "
                            "{%0,%1,%2,%3}, {%4,%5,%6,%7}, {%8,%9}, {%0,%1,%2,%3};"
                            : "+f"(acc[m][j][0]), "+f"(acc[m][j][1]),
                              "+f"(acc[m][j][2]), "+f"(acc[m][j][3])
                            : "r"(a[m][0]), "r"(a[m][1]), "r"(a[m][2]), "r"(a[m][3]),
                              "r"(b0), "r"(b1));
                    }
            }
        }

        // ---- epilogue: H_t = tanh(C + Z_t), packed bf16x2 stores ----
        const float* Zt = Z + (long)t * BB * HH;
        __nv_bfloat16* Ht = H + (long)t * BB * HH;
#pragma unroll
        for (int m = 0; m < 2; m++)
#pragma unroll
            for (int j = 0; j < 4; j++) {
                long grow = rowBase + wm * 32 + m * 16 + r0;
                int  gcol = colBase + wn * 32 + j * 8 + c0;
                long g0 = grow * HH + gcol;
                long g1 = (grow + 8) * HH + gcol;
                float2 z0 = *reinterpret_cast<const float2*>(&Zt[g0]);
                float2 z1 = *reinterpret_cast<const float2*>(&Zt[g1]);
                __nv_bfloat162 h0, h1;
                h0.x = __float2bfloat16(tanhf(acc[m][j][0] + z0.x));
                h0.y = __float2bfloat16(tanhf(acc[m][j][1] + z0.y));
                h1.x = __float2bfloat16(tanhf(acc[m][j][2] + z1.x));
                h1.y = __float2bfloat16(tanhf(acc[m][j][3] + z1.y));
                *reinterpret_cast<__nv_bfloat162*>(&Ht[g0]) = h0;
                *reinterpret_cast<__nv_bfloat162*>(&Ht[g1]) = h1;
            }
    }
}

// ---------------------------------------------------------------------------
// out = sigmoid(Hlast @ Wo + bo), one warp per row
__global__ void head_kernel(const __nv_bfloat16* __restrict__ Hl,
                            const float* __restrict__ Wo,
                            const float* __restrict__ bo,
                            float* __restrict__ out)
{
    int row  = blockIdx.x * 8 + (threadIdx.x >> 5);
    int lane = threadIdx.x & 31;
    float s = 0.f;
    for (int j = lane; j < HH; j += 32)
        s += __bfloat162float(Hl[(long)row * HH + j]) * Wo[j];
#pragma unroll
    for (int o = 16; o > 0; o >>= 1) s += __shfl_xor_sync(0xffffffffu, s, o);
    if (lane == 0) out[row] = 1.f / (1.f + expf(-(s + bo[0])));
}

// ---------------------------------------------------------------------------
extern "C" void kernel_launch(void* const* d_in, const int* in_sizes, int n_in,
                              void* d_out, int out_size)
{
    const int*   tokens = (const int*)d_in[0];
    const float* emb = (const float*)d_in[1];
    const float* W1 = (const float*)d_in[2];
    const float* U1 = (const float*)d_in[3];
    const float* b1 = (const float*)d_in[4];
    const float* W2 = (const float*)d_in[5];
    const float* U2 = (const float*)d_in[6];
    const float* b2 = (const float*)d_in[7];
    const float* W3 = (const float*)d_in[8];
    const float* U3 = (const float*)d_in[9];
    const float* b3 = (const float*)d_in[10];
    const float* W4 = (const float*)d_in[11];
    const float* U4 = (const float*)d_in[12];
    const float* b4 = (const float*)d_in[13];
    const float* Wo = (const float*)d_in[14];
    const float* bo = (const float*)d_in[15];
    float* out = (float*)d_out;

    __nv_bfloat16 *bufA, *bufB, *W1bf, *Wbf, *Ubf;
    float* Zbuf;
    cudaGetSymbolAddress((void**)&bufA, g_bufA);
    cudaGetSymbolAddress((void**)&bufB, g_bufB);
    cudaGetSymbolAddress((void**)&W1bf, g_W1bf);
    cudaGetSymbolAddress((void**)&Wbf, g_Wbf);
    cudaGetSymbolAddress((void**)&Ubf, g_Ubf);
    cudaGetSymbolAddress((void**)&Zbuf, g_Z);

    // opt-in to >48KB dynamic smem (idempotent; legal during capture)
    cudaFuncSetAttribute(rnn_layer_kernel,
                         cudaFuncAttributeMaxDynamicSharedMemorySize, RNN_SMEM);

    const dim3 blk(256);
    convert_weights_kernel<<<(HH * HH + 255) / 256, blk>>>(W1, W2, W3, W4, U1, U2, U3, U4);
    embed_kernel<<<(int)(((long)MT * K1P + 255) / 256), blk>>>(tokens, emb);

    const dim3 gridBig(MT / 128, 8);

    // -------- layer 1 --------
    gemm_z_kernel<<<gridBig, blk>>>(bufA, K1P, K1P, W1bf, b1, Zbuf);
    rnn_layer_kernel<<<NCTAS, blk, RNN_SMEM>>>(Zbuf, bufB, Ubf);

    // -------- layers 2..4 --------
    const float* biases[4] = {b1, b2, b3, b4};
    __nv_bfloat16* Xin  = bufB;
    __nv_bfloat16* Hout = bufA;
    for (int l = 1; l < 4; l++) {
        gemm_z_kernel<<<gridBig, blk>>>(Xin, HH, HH, Wbf + (size_t)(l - 1) * HH * HH,
                                        biases[l], Zbuf);
        rnn_layer_kernel<<<NCTAS, blk, RNN_SMEM>>>(Zbuf, Hout, Ubf + (size_t)l * HH * HH);
        __nv_bfloat16* tmp = Xin; Xin = Hout; Hout = tmp;
    }

    // final hidden state lives in Xin (last swap), timestep TT-1
    head_kernel<<<BB / 8, blk>>>(Xin + (size_t)(TT - 1) * BB * HH, Wo, bo, out);
}

// round 10
// speedup vs baseline: 1.5291x; 1.2250x over previous
#include <cuda_runtime.h>
#include <cuda_bf16.h>
#include <cstdint>
#include <math.h>

#define BB   2048
#define TT   80
#define HH   512
#define EMBD 100
#define K1P  128            // EMB padded to 128 for clean BK=32 tiling
#define MT   (BB*TT)        // 163840 rows
#define NCTAS 128           // persistent kernel grid (16 row-blocks x 8 col-blocks)

// ---- scratch (device globals: allocation-free rule) ----
__device__ __nv_bfloat16 g_bufA[(size_t)MT * HH];   // activations ping
__device__ __nv_bfloat16 g_bufB[(size_t)MT * HH];   // activations pong
__device__ __nv_bfloat16 g_Z[(size_t)MT * HH];      // Z = xW+b, bf16
__device__ __nv_bfloat16 g_W1bf[K1P * HH];          // W1 padded [128,512]
__device__ __nv_bfloat16 g_Wbf[3 * HH * HH];        // W2,W3,W4
__device__ __nv_bfloat16 g_Ubf[4 * HH * HH];        // U1..U4

// per-row-group barrier state: group g uses [g*64] (arrive) and [g*64+32] (gen)
// -> arrive and gen live on separate 128B lines, groups fully decoupled.
__device__ unsigned g_grpBar[16 * 64];

// ---------------------------------------------------------------------------
__device__ __forceinline__ float tanh_fast(float x) {
    float y;
    asm("tanh.approx.f32 %0, %1;" : "=f"(y) : "f"(x));
    return y;
}

__device__ __forceinline__ uint32_t smem_u32(const void* p) {
    return (uint32_t)__cvta_generic_to_shared(p);
}

// ---------------------------------------------------------------------------
__global__ void convert_weights_kernel(
    const float* __restrict__ W1, const float* __restrict__ W2,
    const float* __restrict__ W3, const float* __restrict__ W4,
    const float* __restrict__ U1, const float* __restrict__ U2,
    const float* __restrict__ U3, const float* __restrict__ U4)
{
    int i = blockIdx.x * blockDim.x + threadIdx.x;
    if (i < K1P * HH) {
        int r = i / HH, c = i % HH;
        g_W1bf[i] = __float2bfloat16(r < EMBD ? W1[r * HH + c] : 0.f);
    }
    if (i < HH * HH) {
        g_Wbf[i]               = __float2bfloat16(W2[i]);
        g_Wbf[HH * HH + i]     = __float2bfloat16(W3[i]);
        g_Wbf[2 * HH * HH + i] = __float2bfloat16(W4[i]);
        g_Ubf[i]               = __float2bfloat16(U1[i]);
        g_Ubf[HH * HH + i]     = __float2bfloat16(U2[i]);
        g_Ubf[2 * HH * HH + i] = __float2bfloat16(U3[i]);
        g_Ubf[3 * HH * HH + i] = __float2bfloat16(U4[i]);
    }
}

// Embedding gather, time-major [t*BB + b, K1P], zero-padded cols 100..127
__global__ void embed_kernel(const int* __restrict__ tokens,
                             const float* __restrict__ emb)
{
    long i = (long)blockIdx.x * blockDim.x + threadIdx.x;
    if (i >= (long)MT * K1P) return;
    int row = (int)(i / K1P);
    int c   = (int)(i % K1P);
    int t = row / BB, b = row % BB;
    float v = 0.f;
    if (c < EMBD) v = emb[(long)tokens[b * TT + t] * EMBD + c];
    g_bufA[i] = __float2bfloat16(v);
}

// ---------------------------------------------------------------------------
// Big GEMM: Z = X @ W + b (parallel over all t), bf16 output.
// Block tile 128x64, BK=32, 8 warps (4m x 2n), warp tile 32x32, mma m16n8k16.
__global__ __launch_bounds__(256) void gemm_z_kernel(
    const __nv_bfloat16* __restrict__ A, int lda, int K,
    const __nv_bfloat16* __restrict__ Bm,
    const float* __restrict__ bias,
    __nv_bfloat16* __restrict__ outZ)
{
    constexpr int BM = 128, BN = 64, BK = 32;
    __shared__ __nv_bfloat16 As[BM][BK + 8];
    __shared__ __nv_bfloat16 Bs[BK][BN + 8];

    const int tid  = threadIdx.x;
    const int warp = tid >> 5, lane = tid & 31;
    const int wm = warp >> 1, wn = warp & 1;
    const long rowBase = (long)blockIdx.x * BM;
    const int  colBase = blockIdx.y * BN;

    float acc[2][4][4];
#pragma unroll
    for (int m = 0; m < 2; m++)
#pragma unroll
        for (int j = 0; j < 4; j++)
#pragma unroll
            for (int q = 0; q < 4; q++) acc[m][j][q] = 0.f;

    const int a_r0 = tid >> 2, a_ch = tid & 3;
    const int b_r  = tid >> 3, b_ch = tid & 7;

    const int nkt = K / BK;
    for (int kt = 0; kt < nkt; kt++) {
        const int k0 = kt * BK;
#pragma unroll
        for (int p = 0; p < 2; p++) {
            int r = a_r0 + p * 64;
            *reinterpret_cast<uint4*>(&As[r][a_ch * 8]) =
                *reinterpret_cast<const uint4*>(A + (rowBase + r) * lda + k0 + a_ch * 8);
        }
        *reinterpret_cast<uint4*>(&Bs[b_r][b_ch * 8]) =
            *reinterpret_cast<const uint4*>(Bm + (long)(k0 + b_r) * HH + colBase + b_ch * 8);
        __syncthreads();

#pragma unroll
        for (int ks = 0; ks < 2; ks++) {
            uint32_t a[2][4], b[2][4];
#pragma unroll
            for (int m = 0; m < 2; m++) {
                uint32_t addr = smem_u32(&As[wm * 32 + m * 16 + (lane & 15)][ks * 16 + (lane >> 4) * 8]);
                asm volatile("ldmatrix.sync.aligned.m8n8.x4.shared.b16 {%0,%1,%2,%3}, [%4];"
                             : "=r"(a[m][0]), "=r"(a[m][1]), "=r"(a[m][2]), "=r"(a[m][3])
                             : "r"(addr));
            }
#pragma unroll
            for (int jj = 0; jj < 2; jj++) {
                uint32_t addr = smem_u32(&Bs[ks * 16 + (lane & 15)][wn * 32 + jj * 16 + (lane >> 4) * 8]);
                asm volatile("ldmatrix.sync.aligned.m8n8.x4.trans.shared.b16 {%0,%1,%2,%3}, [%4];"
                             : "=r"(b[jj][0]), "=r"(b[jj][1]), "=r"(b[jj][2]), "=r"(b[jj][3])
                             : "r"(addr));
            }
#pragma unroll
            for (int m = 0; m < 2; m++)
#pragma unroll
                for (int j = 0; j < 4; j++) {
                    uint32_t b0 = b[j >> 1][(j & 1) * 2 + 0];
                    uint32_t b1 = b[j >> 1][(j & 1) * 2 + 1];
                    asm volatile(
                        "mma.sync.aligned.m16n8k16.row.col.f32.bf16.bf16.f32 "
                        "{%0,%1,%2,%3}, {%4,%5,%6,%7}, {%8,%9}, {%0,%1,%2,%3};"
                        : "+f"(acc[m][j][0]), "+f"(acc[m][j][1]),
                          "+f"(acc[m][j][2]), "+f"(acc[m][j][3])
                        : "r"(a[m][0]), "r"(a[m][1]), "r"(a[m][2]), "r"(a[m][3]),
                          "r"(b0), "r"(b1));
                }
        }
        __syncthreads();
    }

    const int r0 = lane >> 2, c0 = (lane & 3) * 2;
#pragma unroll
    for (int m = 0; m < 2; m++)
#pragma unroll
        for (int j = 0; j < 4; j++) {
            long grow = rowBase + wm * 32 + m * 16 + r0;
            int  gcol = colBase + wn * 32 + j * 8 + c0;
            float bv0 = bias[gcol], bv1 = bias[gcol + 1];
            __nv_bfloat162 v0, v1;
            v0.x = __float2bfloat16(acc[m][j][0] + bv0);
            v0.y = __float2bfloat16(acc[m][j][1] + bv1);
            v1.x = __float2bfloat16(acc[m][j][2] + bv0);
            v1.y = __float2bfloat16(acc[m][j][3] + bv1);
            *reinterpret_cast<__nv_bfloat162*>(&outZ[grow * HH + gcol])       = v0;
            *reinterpret_cast<__nv_bfloat162*>(&outZ[(grow + 8) * HH + gcol]) = v1;
        }
}

// ---------------------------------------------------------------------------
// 8-CTA row-group barrier (sense via monotonically increasing generation)
__device__ __forceinline__ void group_barrier(int grp)
{
    __threadfence();          // release: H writes -> L2
    __syncthreads();
    if (threadIdx.x == 0) {
        volatile unsigned* arr = &g_grpBar[grp * 64];
        volatile unsigned* gen = &g_grpBar[grp * 64 + 32];
        unsigned g = *gen;
        if (atomicAdd((unsigned*)arr, 1u) == 7u) {
            *arr = 0;
            __threadfence();                 // reset before gen bump
            *gen = g + 1;                    // release group
        } else {
            int it = 0;
            while (*gen == g) { if (++it > 16) __nanosleep(32); }
        }
        __threadfence();      // acquire side
    }
    __syncthreads();
}

// ---------------------------------------------------------------------------
// cp.async helpers
template <int N>
__device__ __forceinline__ void cp_wait() {
    asm volatile("cp.async.wait_group %0;" :: "n"(N));
}

#define AS_PITCH 520
#define US_PITCH 72
#define RNN_SMEM ((128 * AS_PITCH + 512 * US_PITCH) * 2)

// async-copy one 128-row x 128-k chunk of A into smem (one commit group)
__device__ __forceinline__ void issue_chunk(__nv_bfloat16 (*As)[AS_PITCH],
                                            const __nv_bfloat16* Ag,
                                            int rowBase, int kc, int tid)
{
    const int base_k = kc * 128;
#pragma unroll
    for (int it = 0; it < 8; it++) {
        int i = tid + it * 256;           // 0..2047
        int r = i >> 4, ch = i & 15;
        uint32_t dst = smem_u32(&As[r][base_k + ch * 8]);
        const __nv_bfloat16* src = Ag + (long)(rowBase + r) * HH + base_k + ch * 8;
        asm volatile("cp.async.cg.shared.global [%0], [%1], 16;"
                     :: "r"(dst), "l"(src));
    }
    asm volatile("cp.async.commit_group;" ::: "memory");
}

// MMA over one 128-k chunk (8 k16 sub-steps)
__device__ __forceinline__ void mma_chunk(
    __nv_bfloat16 (*As)[AS_PITCH], __nv_bfloat16 (*Us)[US_PITCH],
    int kbase, int wm, int wn, int lane, float acc[2][4][4])
{
#pragma unroll
    for (int ks = 0; ks < 8; ks++) {
        const int k0 = kbase + ks * 16;
        uint32_t a[2][4], b[2][4];
#pragma unroll
        for (int m = 0; m < 2; m++) {
            uint32_t addr = smem_u32(&As[wm * 32 + m * 16 + (lane & 15)][k0 + (lane >> 4) * 8]);
            asm volatile("ldmatrix.sync.aligned.m8n8.x4.shared.b16 {%0,%1,%2,%3}, [%4];"
                         : "=r"(a[m][0]), "=r"(a[m][1]), "=r"(a[m][2]), "=r"(a[m][3])
                         : "r"(addr));
        }
#pragma unroll
        for (int jj = 0; jj < 2; jj++) {
            uint32_t addr = smem_u32(&Us[k0 + (lane & 15)][wn * 32 + jj * 16 + (lane >> 4) * 8]);
            asm volatile("ldmatrix.sync.aligned.m8n8.x4.trans.shared.b16 {%0,%1,%2,%3}, [%4];"
                         : "=r"(b[jj][0]), "=r"(b[jj][1]), "=r"(b[jj][2]), "=r"(b[jj][3])
                         : "r"(addr));
        }
#pragma unroll
        for (int m = 0; m < 2; m++)
#pragma unroll
            for (int j = 0; j < 4; j++) {
                asm volatile(
                    "mma.sync.aligned.m16n8k16.row.col.f32.bf16.bf16.f32 "
                    "{%0,%1,%2,%3}, {%4,%5,%6,%7}, {%8,%9}, {%0,%1,%2,%3};"
                    : "+f"(acc[m][j][0]), "+f"(acc[m][j][1]),
                      "+f"(acc[m][j][2]), "+f"(acc[m][j][3])
                    : "r"(a[m][0]), "r"(a[m][1]), "r"(a[m][2]), "r"(a[m][3]),
                      "r"(b[j >> 1][(j & 1) * 2]), "r"(b[j >> 1][(j & 1) * 2 + 1]));
            }
    }
}

// ---------------------------------------------------------------------------
// Persistent per-layer recurrence: H_t = tanh(H_{t-1} @ U + Z_t), t = 0..79
// Grid = 128 CTAs (16 row-groups of 8 col-blocks), 256 threads, 1 CTA/SM.
// U[:, col:col+64] resident in smem; A loaded via cp.async pipeline;
// sync only within the 8-CTA row-group (the true dependency set).
__global__ __launch_bounds__(256) void rnn_layer_kernel(
    const __nv_bfloat16* __restrict__ Z,   // [TT][BB][HH] bf16
    __nv_bfloat16* __restrict__ H,         // [TT][BB][HH] bf16 (output)
    const __nv_bfloat16* __restrict__ U)   // [HH][HH] bf16
{
    const int tid  = threadIdx.x;
    const int warp = tid >> 5, lane = tid & 31;
    const int wm = warp >> 1, wn = warp & 1;
    const int grp = blockIdx.x >> 3;
    const int rowBase = grp * 128;
    const int colBase = (blockIdx.x & 7) * 64;

    extern __shared__ __nv_bfloat16 sh[];
    __nv_bfloat16 (*As)[AS_PITCH] = reinterpret_cast<__nv_bfloat16(*)[AS_PITCH]>(sh);
    __nv_bfloat16 (*Us)[US_PITCH] = reinterpret_cast<__nv_bfloat16(*)[US_PITCH]>(sh + 128 * AS_PITCH);

    // ---- load U slice [512][64] into smem once ----
    for (int i = tid; i < 512 * 8; i += 256) {
        int k = i >> 3, ch = i & 7;
        *reinterpret_cast<uint4*>(&Us[k][ch * 8]) =
            *reinterpret_cast<const uint4*>(U + (long)k * HH + colBase + ch * 8);
    }

    // ---- epilogue offsets (constant within a t-slab) ----
    const int r0 = lane >> 2, c0 = (lane & 3) * 2;
    int offs[2][4][2];
#pragma unroll
    for (int m = 0; m < 2; m++)
#pragma unroll
        for (int j = 0; j < 4; j++) {
            int grow = rowBase + wm * 32 + m * 16 + r0;
            int gcol = colBase + wn * 32 + j * 8 + c0;
            offs[m][j][0] = grow * HH + gcol;
            offs[m][j][1] = (grow + 8) * HH + gcol;
        }

    // ---- step 0: H0 = tanh(Z0) for our tile ----
    for (int i = tid; i < 128 * 32; i += 256) {
        int r = i >> 5, c2 = (i & 31) * 2;
        long g = (long)(rowBase + r) * HH + colBase + c2;
        __nv_bfloat162 z = *reinterpret_cast<const __nv_bfloat162*>(&Z[g]);
        __nv_bfloat162 hv;
        hv.x = __float2bfloat16(tanh_fast(__bfloat162float(z.x)));
        hv.y = __float2bfloat16(tanh_fast(__bfloat162float(z.y)));
        *reinterpret_cast<__nv_bfloat162*>(&H[g]) = hv;
    }

    for (int t = 1; t < TT; t++) {
        group_barrier(grp);   // H_{t-1} (this row-group) visible; guards As reuse

        const __nv_bfloat16* Ag = H + (long)(t - 1) * BB * HH;
        const __nv_bfloat16* Zt = Z + (long)t * BB * HH;
        __nv_bfloat16*       Ht = H + (long)t * BB * HH;

        // start the A pipeline
        issue_chunk(As, Ag, rowBase, 0, tid);
        issue_chunk(As, Ag, rowBase, 1, tid);

        // prefetch Z for the epilogue (hide DRAM/L2 latency under MMA)
        uint32_t zp[2][4][2];
#pragma unroll
        for (int m = 0; m < 2; m++)
#pragma unroll
            for (int j = 0; j < 4; j++) {
                zp[m][j][0] = *reinterpret_cast<const uint32_t*>(&Zt[offs[m][j][0]]);
                zp[m][j][1] = *reinterpret_cast<const uint32_t*>(&Zt[offs[m][j][1]]);
            }

        float acc[2][4][4];
#pragma unroll
        for (int m = 0; m < 2; m++)
#pragma unroll
            for (int j = 0; j < 4; j++)
#pragma unroll
                for (int q = 0; q < 4; q++) acc[m][j][q] = 0.f;

        // pipelined: MMA chunk k overlaps load of chunks k+1, k+2
        issue_chunk(As, Ag, rowBase, 2, tid);
        cp_wait<2>(); __syncthreads();
        mma_chunk(As, Us, 0, wm, wn, lane, acc);

        issue_chunk(As, Ag, rowBase, 3, tid);
        cp_wait<2>(); __syncthreads();
        mma_chunk(As, Us, 128, wm, wn, lane, acc);

        cp_wait<1>(); __syncthreads();
        mma_chunk(As, Us, 256, wm, wn, lane, acc);

        cp_wait<0>(); __syncthreads();
        mma_chunk(As, Us, 384, wm, wn, lane, acc);

        // ---- epilogue: H_t = tanh(C + Z_t) ----
#pragma unroll
        for (int m = 0; m < 2; m++)
#pragma unroll
            for (int j = 0; j < 4; j++) {
                __nv_bfloat162 z0 = *reinterpret_cast<__nv_bfloat162*>(&zp[m][j][0]);
                __nv_bfloat162 z1 = *reinterpret_cast<__nv_bfloat162*>(&zp[m][j][1]);
                __nv_bfloat162 h0, h1;
                h0.x = __float2bfloat16(tanh_fast(acc[m][j][0] + __bfloat162float(z0.x)));
                h0.y = __float2bfloat16(tanh_fast(acc[m][j][1] + __bfloat162float(z0.y)));
                h1.x = __float2bfloat16(tanh_fast(acc[m][j][2] + __bfloat162float(z1.x)));
                h1.y = __float2bfloat16(tanh_fast(acc[m][j][3] + __bfloat162float(z1.y)));
                *reinterpret_cast<__nv_bfloat162*>(&Ht[offs[m][j][0]]) = h0;
                *reinterpret_cast<__nv_bfloat162*>(&Ht[offs[m][j][1]]) = h1;
            }
    }
}

// ---------------------------------------------------------------------------
// out = sigmoid(Hlast @ Wo + bo), one warp per row
__global__ void head_kernel(const __nv_bfloat16* __restrict__ Hl,
                            const float* __restrict__ Wo,
                            const float* __restrict__ bo,
                            float* __restrict__ out)
{
    int row  = blockIdx.x * 8 + (threadIdx.x >> 5);
    int lane = threadIdx.x & 31;
    float s = 0.f;
    for (int j = lane; j < HH; j += 32)
        s += __bfloat162float(Hl[(long)row * HH + j]) * Wo[j];
#pragma unroll
    for (int o = 16; o > 0; o >>= 1) s += __shfl_xor_sync(0xffffffffu, s, o);
    if (lane == 0) out[row] = 1.f / (1.f + expf(-(s + bo[0])));
}

// ---------------------------------------------------------------------------
extern "C" void kernel_launch(void* const* d_in, const int* in_sizes, int n_in,
                              void* d_out, int out_size)
{
    const int*   tokens = (const int*)d_in[0];
    const float* emb = (const float*)d_in[1];
    const float* W1 = (const float*)d_in[2];
    const float* U1 = (const float*)d_in[3];
    const float* b1 = (const float*)d_in[4];
    const float* W2 = (const float*)d_in[5];
    const float* U2 = (const float*)d_in[6];
    const float* b2 = (const float*)d_in[7];
    const float* W3 = (const float*)d_in[8];
    const float* U3 = (const float*)d_in[9];
    const float* b3 = (const float*)d_in[10];
    const float* W4 = (const float*)d_in[11];
    const float* U4 = (const float*)d_in[12];
    const float* b4 = (const float*)d_in[13];
    const float* Wo = (const float*)d_in[14];
    const float* bo = (const float*)d_in[15];
    float* out = (float*)d_out;

    __nv_bfloat16 *bufA, *bufB, *W1bf, *Wbf, *Ubf, *Zbuf;
    cudaGetSymbolAddress((void**)&bufA, g_bufA);
    cudaGetSymbolAddress((void**)&bufB, g_bufB);
    cudaGetSymbolAddress((void**)&W1bf, g_W1bf);
    cudaGetSymbolAddress((void**)&Wbf, g_Wbf);
    cudaGetSymbolAddress((void**)&Ubf, g_Ubf);
    cudaGetSymbolAddress((void**)&Zbuf, g_Z);

    cudaFuncSetAttribute(rnn_layer_kernel,
                         cudaFuncAttributeMaxDynamicSharedMemorySize, RNN_SMEM);

    const dim3 blk(256);
    convert_weights_kernel<<<(HH * HH + 255) / 256, blk>>>(W1, W2, W3, W4, U1, U2, U3, U4);
    embed_kernel<<<(int)(((long)MT * K1P + 255) / 256), blk>>>(tokens, emb);

    const dim3 gridBig(MT / 128, 8);

    // -------- layer 1 --------
    gemm_z_kernel<<<gridBig, blk>>>(bufA, K1P, K1P, W1bf, b1, Zbuf);
    rnn_layer_kernel<<<NCTAS, blk, RNN_SMEM>>>(Zbuf, bufB, Ubf);

    // -------- layers 2..4 --------
    const float* biases[4] = {b1, b2, b3, b4};
    __nv_bfloat16* Xin  = bufB;
    __nv_bfloat16* Hout = bufA;
    for (int l = 1; l < 4; l++) {
        gemm_z_kernel<<<gridBig, blk>>>(Xin, HH, HH, Wbf + (size_t)(l - 1) * HH * HH,
                                        biases[l], Zbuf);
        rnn_layer_kernel<<<NCTAS, blk, RNN_SMEM>>>(Zbuf, Hout, Ubf + (size_t)l * HH * HH);
        __nv_bfloat16* tmp = Xin; Xin = Hout; Hout = tmp;
    }

    // final hidden state lives in Xin (last swap), timestep TT-1
    head_kernel<<<BB / 8, blk>>>(Xin + (size_t)(TT - 1) * BB * HH, Wo, bo, out);
}